// round 12
// baseline (speedup 1.0000x reference)
#include <cuda_runtime.h>
#include <cuda_bf16.h>

// ---------------- problem constants ----------------
#define N0 6912      // 48*48*3
#define N1 27648     // 96*96*3
#define N2 110592    // 192*192*3
#define NTOT 145152
#define MAXB 100
#define CCAP 4096
#define S_TAIL 256u
#define HBINS 8192   // 13-bit conf histogram
#define GBLK 142     // 142*1024 >= NTOT
// K1 geometry: warp per 4 boxes, direct loads
#define TW 36288     // NTOT/4
#define NB1 2268     // TW/16 (16 warps per block)
// K4
#define K4T 256
#define K4SM 114688  // A(32KB) + SL(16KB) + sBox(64KB)

// ---------------- scratch (device globals; zero-initialized at load) ----------------
__device__ float    g_conf[NTOT];
__device__ unsigned g_keysA[NTOT];        // fallback-only scratch
__device__ unsigned g_hist13[HBINS];      // zeroed by k4 self-clean
__device__ unsigned g_candK[CCAP], g_candV[CCAP];
__device__ float4   g_candBox[CCAP];
__device__ int      g_candCls[CCAP];
__device__ float4   g_bboxFB[NTOT];       // fallback-only scratch
__device__ float    g_partM[NB1], g_partm[NB1];
__device__ unsigned g_totalvalid;
__device__ unsigned g_ticket, g_overflow;

// order-preserving float<->uint encodings
__device__ __forceinline__ unsigned enc_ord(float f) {
    unsigned u = __float_as_uint(f);
    return (u & 0x80000000u) ? ~u : (u ^ 0x80000000u);
}
__device__ __forceinline__ float dec_ord(unsigned o) {
    unsigned u = (o & 0x80000000u) ? (o ^ 0x80000000u) : ~o;
    return __uint_as_float(u);
}

// Exact-equivalent IoU>0.5 test: fast multiply compare with a 1e-4 relative
// guard band; inside the band fall back to the reference's rounded division.
__device__ __forceinline__ bool iou_gt_half(float4 a, float areaA, float4 b, float areaB) {
    float iw = fminf(a.z, b.z) - fmaxf(a.x, b.x); iw = fmaxf(iw, 0.0f);
    float ih = fminf(a.w, b.w) - fmaxf(a.y, b.y); ih = fmaxf(ih, 0.0f);
    float inter = iw * ih;
    float U = areaA + areaB - inter;
    float d = inter - 0.5f * U;
    if (fabsf(d) > 1e-4f * U) return d > 0.0f;
    return __fdiv_rn(inter, U) > 0.5f;
}

__device__ __forceinline__ const float* box_ptr(int gw,
        const float* g0, const float* g1, const float* g2,
        int& H, int& abase, int& local) {
    if (gw < N0)      { H = 48;  abase = 12; local = gw;           return g0 + (size_t)local * 85; }
    if (gw < N0 + N1) { H = 96;  abase = 6;  local = gw - N0;      return g1 + (size_t)local * 85; }
    H = 192; abase = 0; local = gw - N0 - N1; return g2 + (size_t)local * 85;
}

__device__ __forceinline__ float4 geom(const float* p, int local, int H, int abase,
                                       const float* anch) {
    float x = p[0], y = p[1], wv = p[2], hv = p[3];
    int a = local % 3;
    int cell = local / 3;
    int cx = cell % H;   // W == H
    int cy = cell / H;
    float aw = anch[abase + a * 2 + 0];
    float ah = anch[abase + a * 2 + 1];
    float bw = expf(wv) * aw;
    float bh = expf(hv) * ah;
    float Hf = (float)H;
    float X = __fdiv_rn(x + (float)cx, Hf);
    float Y = __fdiv_rn(y + (float)cy, Hf);
    return make_float4(X - bw * 0.5f, Y - bh * 0.5f, X + bw * 0.5f, Y + bh * 0.5f);
}

// ---------------- K1: direct-load streaming conf + conf-hist + per-block M/m ----------------
__global__ void __launch_bounds__(512)
k1_kernel(const float* __restrict__ g0,
          const float* __restrict__ g1,
          const float* __restrict__ g2) {
    const int tid = threadIdx.x;
    const int lane = tid & 31;
    const int wid = tid >> 5;
    const int w = blockIdx.x * 16 + wid;   // 0..TW-1

    float bv[4], cf[4];
    int gws[4];
    #pragma unroll
    for (int it = 0; it < 4; ++it) {
        int gw = w + it * TW;
        gws[it] = gw;
        int H, abase, local;
        const float* p = box_ptr(gw, g0, g1, g2, H, abase, local);
        float v0 = p[5 + lane];
        float v1 = p[37 + lane];
        float v2 = (lane < 16) ? p[69 + lane] : -3.4e38f;
        bv[it] = fmaxf(fmaxf(v0, v1), v2);
        cf[it] = (lane == 0) ? p[4] : 0.0f;
    }
    #pragma unroll
    for (int it = 0; it < 4; ++it) {
        #pragma unroll
        for (int off = 16; off; off >>= 1)
            bv[it] = fmaxf(bv[it], __shfl_xor_sync(0xffffffffu, bv[it], off));
    }
    if (lane == 0) {
        #pragma unroll
        for (int it = 0; it < 4; ++it) {
            g_conf[gws[it]] = cf[it];
            atomicAdd(&g_hist13[enc_ord(cf[it]) >> 19], 1u);
        }
    }

    float M = fmaxf(fmaxf(bv[0], bv[1]), fmaxf(bv[2], bv[3]));
    float m = fminf(fminf(bv[0], bv[1]), fminf(bv[2], bv[3]));
    __shared__ float aM[16], am[16];
    if (lane == 0) { aM[wid] = M; am[wid] = m; }
    __syncthreads();
    if (tid == 0) {
        #pragma unroll
        for (int i = 1; i < 16; ++i) { M = fmaxf(M, aM[i]); m = fminf(m, am[i]); }
        g_partM[blockIdx.x] = M;
        g_partm[blockIdx.x] = m;
    }
}

// ---------------- K3: per-block two-tail cutoff + compact + warp-cooperative decode ----------------
__global__ void __launch_bounds__(1024)
k3_kernel(const float* __restrict__ g0,
          const float* __restrict__ g1,
          const float* __restrict__ g2,
          const float* __restrict__ anch) {
    __shared__ unsigned s_hist[HBINS];   // 32KB
    __shared__ unsigned s_part[1024];    // 4KB
    __shared__ float s_rM[32], s_rm[32];
    __shared__ float s_MM, s_mm;
    __shared__ int s_posthr, s_negthr;

    const int tid = threadIdx.x;
    const int lane = tid & 31;
    const int wid = tid >> 5;

    // ---- reduce partial M/m (all blocks redundantly) ----
    {
        float M = -3.4e38f, m = 3.4e38f;
        for (int i = tid; i < NB1; i += 1024) {
            M = fmaxf(M, g_partM[i]);
            m = fminf(m, g_partm[i]);
        }
        #pragma unroll
        for (int off = 16; off; off >>= 1) {
            M = fmaxf(M, __shfl_xor_sync(0xffffffffu, M, off));
            m = fminf(m, __shfl_xor_sync(0xffffffffu, m, off));
        }
        if (lane == 0) { s_rM[wid] = M; s_rm[wid] = m; }
        __syncthreads();
        if (tid == 0) {
            #pragma unroll
            for (int i = 1; i < 32; ++i) { M = fmaxf(M, s_rM[i]); m = fminf(m, s_rm[i]); }
            s_MM = M; s_mm = m;
            s_posthr = 0x7FFFFFFF;
            s_negthr = -1;
        }
    }

    // ---- load conf-hist, prefix sums ----
    #pragma unroll
    for (int i = 0; i < HBINS / 1024; ++i)
        s_hist[tid + i * 1024] = g_hist13[tid + i * 1024];
    __syncthreads();
    unsigned part = 0;
    #pragma unroll
    for (int i = 0; i < 8; ++i) part += s_hist[tid * 8 + i];
    s_part[tid] = part;
    __syncthreads();
    unsigned x = part;
    for (int off = 1; off < 1024; off <<= 1) {
        unsigned add = (tid >= off) ? s_part[tid - off] : 0u;
        __syncthreads();
        x += add;
        s_part[tid] = x;
        __syncthreads();
    }
    const unsigned TOT = s_part[1023];
    const unsigned totalneg = s_part[511];         // bins 0..4095 (c<0 incl -0)
    const unsigned totalpos = TOT - totalneg;      // bins 4096..8191 (c>0 incl +0)
    const float M = s_MM, m = s_mm;

    // ---- neg tail threshold (valid iff m<0): top scores = most negative conf = lowest bins ----
    if (m < 0.0f && totalneg > 0) {
        unsigned Sn = S_TAIL < totalneg ? S_TAIL : totalneg;
        if (tid < 512) {
            unsigned prev = (tid == 0) ? 0u : s_part[tid - 1];
            if (x >= Sn && prev < Sn) {
                unsigned run = prev;
                #pragma unroll
                for (int i = 0; i < 8; ++i) {
                    run += s_hist[tid * 8 + i];
                    if (run >= Sn) { s_negthr = tid * 8 + i; break; }
                }
            }
        }
    }
    // ---- pos tail threshold (valid iff M>0): top scores = highest conf = highest bins ----
    if (M > 0.0f && totalpos > 0) {
        unsigned Sp = S_TAIL < totalpos ? S_TAIL : totalpos;
        if (tid >= 512) {
            unsigned above_end = TOT - x;                       // bins > 8*tid+7
            unsigned above_start = TOT - s_part[tid - 1];      // bins >= 8*tid
            if (above_end < Sp && above_start >= Sp) {
                unsigned run = above_end;
                #pragma unroll
                for (int i = 7; i >= 0; --i) {
                    run += s_hist[tid * 8 + i];
                    if (run >= Sp) { s_posthr = tid * 8 + i; break; }
                }
            }
        }
    }
    __syncthreads();
    int posthr = s_posthr, negthr = s_negthr;

    if (blockIdx.x == 0 && tid == 0) {
        unsigned tv = 0;
        if (M > 0.0f) tv += totalpos;   // upper bound on valid count
        if (m < 0.0f) tv += totalneg;
        g_totalvalid = tv;
    }

    // ---- compact + warp-cooperative decode ----
    int i = blockIdx.x * 1024 + tid;
    bool inb = (i < NTOT);
    float c = inb ? g_conf[i] : 0.0f;
    int bin = (int)(enc_ord(c) >> 19);
    bool take = inb && (bin >= posthr || bin <= negthr);
    unsigned key = 0u;
    if (take) {
        float score = fmaxf(c * M, c * m);
        if (score > 0.0f) key = ~enc_ord(score);
        else take = false;
    }
    unsigned pos = 0;
    if (take) {
        pos = atomicAdd(&g_ticket, 1u);
        if (pos < CCAP) { g_candK[pos] = key; g_candV[pos] = (unsigned)i; }
        else            { g_overflow = 1u; take = false; }
    }
    unsigned tb = __ballot_sync(0xffffffffu, take);
    while (tb) {
        int src = __ffs(tb) - 1; tb &= tb - 1;
        int cgw = (int)__shfl_sync(0xffffffffu, (unsigned)i, src);
        unsigned cpos = __shfl_sync(0xffffffffu, pos, src);
        int H, abase, local;
        const float* p = box_ptr(cgw, g0, g1, g2, H, abase, local);
        float bvv = -3.4e38f;
        int bi = 0;
        for (int cc = lane; cc < 80; cc += 32) {
            float v = p[5 + cc];
            if (v > bvv) { bvv = v; bi = cc; }
        }
        #pragma unroll
        for (int off = 16; off; off >>= 1) {
            float ov = __shfl_xor_sync(0xffffffffu, bvv, off);
            int   oi = __shfl_xor_sync(0xffffffffu, bi, off);
            if (ov > bvv || (ov == bvv && oi < bi)) { bvv = ov; bi = oi; }
        }
        if (lane == 0) {
            g_candBox[cpos] = geom(p, local, H, abase, anch);
            g_candCls[cpos] = bi;
        }
    }
}

// ---------------- K4: 256-thread tail: bitonic sort + matrix NMS + output + self-clean ----------------
__global__ void __launch_bounds__(K4T, 1)
k4_kernel(const float* __restrict__ g0,
          const float* __restrict__ g1,
          const float* __restrict__ g2,
          const float* __restrict__ anch,
          float* __restrict__ out, int out_size) {
    extern __shared__ unsigned char DS[];
    unsigned long long* A = (unsigned long long*)DS;        // 32KB (4096 u64)
    unsigned* SL = (unsigned*)(DS + 32768);                 // 16KB
    float4*  sBox = (float4*)(DS + 49152);                  // 64KB

    __shared__ unsigned mat[K4T][8];      // suppression bitmatrix (8KB)
    __shared__ float s_areaC[K4T];
    __shared__ unsigned s_alive[8];
    __shared__ int s_opos[MAXB];
    __shared__ int s_fbidx[MAXB];
    __shared__ float4 selB[MAXB];
    __shared__ float  selA[MAXB];
    __shared__ float4 o_box[MAXB];
    __shared__ float  o_score[MAXB];
    __shared__ int    o_cls[MAXB];
    __shared__ float  s_fM[K4T], s_fm[K4T];
    __shared__ int s_nsel;

    const int tid = threadIdx.x;
    const int lane = tid & 31;
    const int wid = tid >> 5;

    unsigned totalvalid = g_totalvalid;
    int C = (int)(g_ticket < (unsigned)CCAP ? g_ticket : (unsigned)CCAP);
    int ovf = (int)g_overflow;
    if (tid == 0) s_nsel = 0;
    __syncthreads();

    if (C > 0) {
        int NP = 128;
        while (NP < C) NP <<= 1;   // <= CCAP = 4096

        for (int i = tid; i < NP; i += K4T) {
            if (i < C) { A[i] = ((unsigned long long)g_candK[i] << 32) | g_candV[i]; SL[i] = (unsigned)i; }
            else       { A[i] = ~0ull; SL[i] = 0u; }
        }
        __syncthreads();

        // ---- bitonic sort ascending on (key, boxidx): exact order + tie-break ----
        for (int k = 2; k <= NP; k <<= 1) {
            for (int j = k >> 1; j > 0; j >>= 1) {
                for (int i = tid; i < NP; i += K4T) {
                    int ixj = i ^ j;
                    if (ixj > i) {
                        bool up = ((i & k) == 0);
                        unsigned long long a = A[i], bb = A[ixj];
                        if ((up && a > bb) || (!up && a < bb)) {
                            A[i] = bb; A[ixj] = a;
                            unsigned t = SL[i]; SL[i] = SL[ixj]; SL[ixj] = t;
                        }
                    }
                }
                __syncthreads();
            }
        }

        // ---- gather candidate boxes in sorted order ----
        for (int i = tid; i < C; i += K4T) sBox[i] = g_candBox[SL[i]];
        __syncthreads();

        // ---- chunked matrix NMS ----
        for (int base = 0; base < C; base += K4T) {
            int t = base + tid;
            int lim = (C - base) < K4T ? (C - base) : K4T;
            bool alive = (tid < lim);
            float4 bx = make_float4(0.f, 0.f, 0.f, 0.f);
            float ar = 0.f;
            if (alive) {
                bx = sBox[t];
                ar = (bx.z - bx.x) * (bx.w - bx.y);
            }
            s_areaC[tid] = ar;
            if (alive) {
                int n0 = s_nsel;
                for (int s = 0; s < n0; ++s) {
                    if (iou_gt_half(bx, ar, selB[s], selA[s])) { alive = false; break; }
                }
            }
            __syncthreads();

            unsigned row[8] = {0u,0u,0u,0u,0u,0u,0u,0u};
            if (alive) {
                for (int j = tid + 1; j < lim; ++j) {
                    float4 ob = sBox[base + j];
                    if (iou_gt_half(bx, ar, ob, s_areaC[j])) row[j >> 5] |= 1u << (j & 31);
                }
            }
            #pragma unroll
            for (int q = 0; q < 8; ++q) mat[tid][q] = row[q];

            unsigned bal = __ballot_sync(0xffffffffu, alive);
            if (lane == 0) s_alive[wid] = bal;
            __syncthreads();

            if (wid == 0) {
                int nsel = s_nsel;
                unsigned aw = (lane < 8) ? s_alive[lane] : 0u;
                while (nsel < MAXB) {
                    unsigned nz = __ballot_sync(0xffffffffu, aw != 0u);
                    if (!nz) break;
                    int fw = __ffs(nz) - 1;
                    unsigned w = __shfl_sync(0xffffffffu, aw, fw);
                    int fb = __ffs(w) - 1;
                    int f = (fw << 5) + fb;
                    if (lane < 8) {
                        aw &= ~mat[f][lane];
                        if (lane == fw) aw &= ~(1u << fb);
                    }
                    if (lane == 0) {
                        int gp = base + f;
                        s_opos[nsel] = gp;
                        float4 sbx = sBox[gp];
                        selB[nsel] = sbx;
                        selA[nsel] = (sbx.z - sbx.x) * (sbx.w - sbx.y);
                    }
                    nsel++;
                }
                if (lane == 0) s_nsel = nsel;
            }
            __syncthreads();
            if (s_nsel >= MAXB) break;
        }

        // ---- fill output arrays ----
        int ns = s_nsel;
        for (int j = tid; j < ns; j += K4T) {
            int i = s_opos[j];
            o_box[j]   = sBox[i];
            o_score[j] = dec_ord(~(unsigned)(A[i] >> 32));
            o_cls[j]   = g_candCls[SL[i]];
        }
        __syncthreads();
    }

    // ================= fallback (exactness guard; normally never taken) =================
    {
        bool need_fb = (s_nsel < MAXB) && (ovf || totalvalid > (unsigned)C);
        if (need_fb) {
            // reduce M/m from partials
            float M = -3.4e38f, m = 3.4e38f;
            for (int i = tid; i < NB1; i += K4T) {
                M = fmaxf(M, g_partM[i]);
                m = fminf(m, g_partm[i]);
            }
            s_fM[tid] = M; s_fm[tid] = m;
            __syncthreads();
            for (int off = K4T / 2; off; off >>= 1) {
                if (tid < off) {
                    s_fM[tid] = fmaxf(s_fM[tid], s_fM[tid + off]);
                    s_fm[tid] = fminf(s_fm[tid], s_fm[tid + off]);
                }
                __syncthreads();
            }
            M = s_fM[0]; m = s_fm[0];
            // compute keys + decode all bboxes
            for (int gw = tid; gw < NTOT; gw += K4T) {
                float c = g_conf[gw];
                float score = fmaxf(c * M, c * m);
                g_keysA[gw] = (score > 0.0f) ? ~enc_ord(score) : 0xFFFFFFFFu;
                int H, abase, local;
                const float* p = box_ptr(gw, g0, g1, g2, H, abase, local);
                g_bboxFB[gw] = geom(p, local, H, abase, anch);
            }
            if (tid == 0) s_nsel = 0;
            __syncthreads();
            unsigned long long* red = A;
            for (int r = 0; r < MAXB; ++r) {
                unsigned long long best = ~0ull;
                for (int i = tid; i < NTOT; i += K4T) {
                    unsigned k = g_keysA[i];
                    if (k < 0x80000000u) {
                        unsigned long long cmp = ((unsigned long long)k << 32) | (unsigned)i;
                        if (cmp < best) best = cmp;
                    }
                }
                red[tid] = best;
                __syncthreads();
                for (int off = K4T / 2; off; off >>= 1) {
                    if (tid < off && red[tid + off] < red[tid]) red[tid] = red[tid + off];
                    __syncthreads();
                }
                best = red[0];
                __syncthreads();
                if (best == ~0ull) break;
                unsigned j = (unsigned)(best & 0xFFFFFFFFu);
                float4 bj = g_bboxFB[j];
                float aj = (bj.z - bj.x) * (bj.w - bj.y);
                if (tid == 0) {
                    int n = s_nsel;
                    o_box[n]   = bj;
                    o_score[n] = dec_ord(~(unsigned)(best >> 32));
                    s_fbidx[n] = (int)j;
                    s_nsel = n + 1;
                }
                for (int i = tid; i < NTOT; i += K4T) {
                    unsigned k = g_keysA[i];
                    if (k < 0x80000000u) {
                        float4 bi = g_bboxFB[i];
                        float ai = (bi.z - bi.x) * (bi.w - bi.y);
                        if (iou_gt_half(bi, ai, bj, aj)) g_keysA[i] = 0xFFFFFFFFu;
                    }
                }
                __syncthreads();
            }
            for (int j2 = tid; j2 < s_nsel; j2 += K4T) {
                int gw = s_fbidx[j2];
                int H, abase, local;
                const float* p = box_ptr(gw, g0, g1, g2, H, abase, local);
                float bestv = -3.4e38f; int bi = 0;
                for (int cc = 0; cc < 80; ++cc) {
                    float v = p[5 + cc];
                    if (v > bestv) { bestv = v; bi = cc; }
                }
                o_cls[j2] = bi;
            }
            __syncthreads();
        }
    }

    // ================= output =================
    int ns = s_nsel;
    for (int i = tid; i < out_size; i += K4T) {
        float v = 0.0f;
        if (i < 400) {
            int j = i >> 2;
            if (j < ns) v = ((float*)o_box)[i];
        } else if (i < 500) {
            int j = i - 400;
            if (j < ns) v = o_score[j];
        } else if (i < 600) {
            int j = i - 500;
            if (j < ns) v = (float)o_cls[j];
        } else if (i == 600) {
            v = (float)ns;
        }
        out[i] = v;
    }

    // ---- self-clean persistent state for next launch ----
    __syncthreads();
    for (int i = tid; i < HBINS; i += K4T) g_hist13[i] = 0u;
    if (tid == 0) {
        g_ticket = 0u;
        g_overflow = 0u;
    }
}

// ---------------- launch ----------------
extern "C" void kernel_launch(void* const* d_in, const int* in_sizes, int n_in,
                              void* d_out, int out_size) {
    const float* g0   = (const float*)d_in[0];
    const float* g1   = (const float*)d_in[1];
    const float* g2   = (const float*)d_in[2];
    const float* anch = (const float*)d_in[3];
    float* out = (float*)d_out;

    cudaFuncSetAttribute(k4_kernel, cudaFuncAttributeMaxDynamicSharedMemorySize, K4SM);

    k1_kernel<<<NB1, 512>>>(g0, g1, g2);
    k3_kernel<<<GBLK, 1024>>>(g0, g1, g2, anch);
    k4_kernel<<<1, K4T, K4SM>>>(g0, g1, g2, anch, out, out_size);
}

// round 13
// speedup vs baseline: 1.1036x; 1.1036x over previous
#include <cuda_runtime.h>
#include <cuda_bf16.h>

// ---------------- problem constants ----------------
#define N0 6912      // 48*48*3
#define N1 27648     // 96*96*3
#define N2 110592    // 192*192*3
#define NTOT 145152
#define MAXB 100
#define CCAP 4096
#define S_TAIL 256u
#define HBINS 8192   // 13-bit conf histogram
#define GBLK 142     // 142*1024 >= NTOT
// K1 geometry: 128 boxes per block, smem-staged
#define NB1 1134     // NTOT/128
#define BPB 128      // boxes per K1 block
#define K1T 256
#define K1SM (BPB * 85 * 4)   // 43520 bytes
// K4
#define K4T 256
#define K4SM 114688  // A(32KB) + SL(16KB) + sBox(64KB)

// ---------------- scratch (device globals; zero-initialized at load) ----------------
__device__ float    g_conf[NTOT];
__device__ unsigned g_keysA[NTOT];        // fallback-only scratch
__device__ unsigned g_hist13[HBINS];      // zeroed by k4 self-clean
__device__ unsigned g_candK[CCAP], g_candV[CCAP];
__device__ float4   g_candBox[CCAP];
__device__ int      g_candCls[CCAP];
__device__ float4   g_bboxFB[NTOT];       // fallback-only scratch
__device__ float    g_partM[NB1], g_partm[NB1];
__device__ unsigned g_totalvalid;
__device__ unsigned g_ticket, g_overflow;

// order-preserving float<->uint encodings
__device__ __forceinline__ unsigned enc_ord(float f) {
    unsigned u = __float_as_uint(f);
    return (u & 0x80000000u) ? ~u : (u ^ 0x80000000u);
}
__device__ __forceinline__ float dec_ord(unsigned o) {
    unsigned u = (o & 0x80000000u) ? (o ^ 0x80000000u) : ~o;
    return __uint_as_float(u);
}

// Exact-equivalent IoU>0.5 test: fast multiply compare with a 1e-4 relative
// guard band; inside the band fall back to the reference's rounded division.
__device__ __forceinline__ bool iou_gt_half(float4 a, float areaA, float4 b, float areaB) {
    float iw = fminf(a.z, b.z) - fmaxf(a.x, b.x); iw = fmaxf(iw, 0.0f);
    float ih = fminf(a.w, b.w) - fmaxf(a.y, b.y); ih = fmaxf(ih, 0.0f);
    float inter = iw * ih;
    float U = areaA + areaB - inter;
    float d = inter - 0.5f * U;
    if (fabsf(d) > 1e-4f * U) return d > 0.0f;
    return __fdiv_rn(inter, U) > 0.5f;
}

__device__ __forceinline__ const float* box_ptr(int gw,
        const float* g0, const float* g1, const float* g2,
        int& H, int& abase, int& local) {
    if (gw < N0)      { H = 48;  abase = 12; local = gw;           return g0 + (size_t)local * 85; }
    if (gw < N0 + N1) { H = 96;  abase = 6;  local = gw - N0;      return g1 + (size_t)local * 85; }
    H = 192; abase = 0; local = gw - N0 - N1; return g2 + (size_t)local * 85;
}

__device__ __forceinline__ float4 geom(const float* p, int local, int H, int abase,
                                       const float* anch) {
    float x = p[0], y = p[1], wv = p[2], hv = p[3];
    int a = local % 3;
    int cell = local / 3;
    int cx = cell % H;   // W == H
    int cy = cell / H;
    float aw = anch[abase + a * 2 + 0];
    float ah = anch[abase + a * 2 + 1];
    float bw = expf(wv) * aw;
    float bh = expf(hv) * ah;
    float Hf = (float)H;
    float X = __fdiv_rn(x + (float)cx, Hf);
    float Y = __fdiv_rn(y + (float)cy, Hf);
    return make_float4(X - bw * 0.5f, Y - bh * 0.5f, X + bw * 0.5f, Y + bh * 0.5f);
}

// ---------------- K1: smem-staged (128-box blocks) conf + conf-hist + per-block M/m ----------------
__global__ void __launch_bounds__(K1T)
k1_kernel(const float* __restrict__ g0,
          const float* __restrict__ g1,
          const float* __restrict__ g2) {
    extern __shared__ float S[];
    const int b = blockIdx.x;
    const int tid = threadIdx.x;
    const int lane = tid & 31;
    const int wid = tid >> 5;

    const float* src; int boxbase; int gbase;
    if (b < 54)       { src = g0; boxbase = b * BPB;         gbase = 0; }
    else if (b < 270) { src = g1; boxbase = (b - 54) * BPB;  gbase = N0; }
    else              { src = g2; boxbase = (b - 270) * BPB; gbase = N0 + N1; }

    const float4* in = (const float4*)(src + (size_t)boxbase * 85);
    float4* S4 = (float4*)S;
    const int NF4 = BPB * 85 / 4;   // 2720
    #pragma unroll 4
    for (int i = tid; i < NF4; i += K1T) S4[i] = in[i];
    __syncthreads();

    // 2 threads per box: halves of the 80 class probs
    int box = tid >> 1, half = tid & 1;
    const float* pb = S + box * 85;
    float mx = -3.4e38f;
    int base = 5 + half * 40;
    #pragma unroll 8
    for (int i = 0; i < 40; ++i) mx = fmaxf(mx, pb[base + i]);
    mx = fmaxf(mx, __shfl_xor_sync(0xffffffffu, mx, 1));
    if (half == 0) {
        float c = pb[4];
        g_conf[gbase + boxbase + box] = c;
        atomicAdd(&g_hist13[enc_ord(c) >> 19], 1u);
    }

    float M = mx, m = mx;
    #pragma unroll
    for (int off = 16; off > 1; off >>= 1) {
        M = fmaxf(M, __shfl_xor_sync(0xffffffffu, M, off));
        m = fminf(m, __shfl_xor_sync(0xffffffffu, m, off));
    }
    __shared__ float aM[8], am[8];
    if (lane == 0) { aM[wid] = M; am[wid] = m; }
    __syncthreads();
    if (tid == 0) {
        #pragma unroll
        for (int i = 1; i < 8; ++i) { M = fmaxf(M, aM[i]); m = fminf(m, am[i]); }
        g_partM[b] = M;
        g_partm[b] = m;
    }
}

// ---------------- K3: per-block two-tail cutoff + compact + warp-cooperative decode ----------------
__global__ void __launch_bounds__(1024)
k3_kernel(const float* __restrict__ g0,
          const float* __restrict__ g1,
          const float* __restrict__ g2,
          const float* __restrict__ anch) {
    __shared__ unsigned s_hist[HBINS];   // 32KB
    __shared__ unsigned s_part[1024];    // 4KB
    __shared__ float s_rM[32], s_rm[32];
    __shared__ float s_MM, s_mm;
    __shared__ int s_posthr, s_negthr;

    const int tid = threadIdx.x;
    const int lane = tid & 31;
    const int wid = tid >> 5;

    // ---- reduce partial M/m (all blocks redundantly) ----
    {
        float M = -3.4e38f, m = 3.4e38f;
        for (int i = tid; i < NB1; i += 1024) {
            M = fmaxf(M, g_partM[i]);
            m = fminf(m, g_partm[i]);
        }
        #pragma unroll
        for (int off = 16; off; off >>= 1) {
            M = fmaxf(M, __shfl_xor_sync(0xffffffffu, M, off));
            m = fminf(m, __shfl_xor_sync(0xffffffffu, m, off));
        }
        if (lane == 0) { s_rM[wid] = M; s_rm[wid] = m; }
        __syncthreads();
        if (tid == 0) {
            #pragma unroll
            for (int i = 1; i < 32; ++i) { M = fmaxf(M, s_rM[i]); m = fminf(m, s_rm[i]); }
            s_MM = M; s_mm = m;
            s_posthr = 0x7FFFFFFF;
            s_negthr = -1;
        }
    }

    // ---- load conf-hist, prefix sums ----
    #pragma unroll
    for (int i = 0; i < HBINS / 1024; ++i)
        s_hist[tid + i * 1024] = g_hist13[tid + i * 1024];
    __syncthreads();
    unsigned part = 0;
    #pragma unroll
    for (int i = 0; i < 8; ++i) part += s_hist[tid * 8 + i];
    s_part[tid] = part;
    __syncthreads();
    unsigned x = part;
    for (int off = 1; off < 1024; off <<= 1) {
        unsigned add = (tid >= off) ? s_part[tid - off] : 0u;
        __syncthreads();
        x += add;
        s_part[tid] = x;
        __syncthreads();
    }
    const unsigned TOT = s_part[1023];
    const unsigned totalneg = s_part[511];         // bins 0..4095 (c<0 incl -0)
    const unsigned totalpos = TOT - totalneg;      // bins 4096..8191 (c>0 incl +0)
    const float M = s_MM, m = s_mm;

    // ---- neg tail threshold (valid iff m<0): top scores = most negative conf = lowest bins ----
    if (m < 0.0f && totalneg > 0) {
        unsigned Sn = S_TAIL < totalneg ? S_TAIL : totalneg;
        if (tid < 512) {
            unsigned prev = (tid == 0) ? 0u : s_part[tid - 1];
            if (x >= Sn && prev < Sn) {
                unsigned run = prev;
                #pragma unroll
                for (int i = 0; i < 8; ++i) {
                    run += s_hist[tid * 8 + i];
                    if (run >= Sn) { s_negthr = tid * 8 + i; break; }
                }
            }
        }
    }
    // ---- pos tail threshold (valid iff M>0): top scores = highest conf = highest bins ----
    if (M > 0.0f && totalpos > 0) {
        unsigned Sp = S_TAIL < totalpos ? S_TAIL : totalpos;
        if (tid >= 512) {
            unsigned above_end = TOT - x;                       // bins > 8*tid+7
            unsigned above_start = TOT - s_part[tid - 1];      // bins >= 8*tid
            if (above_end < Sp && above_start >= Sp) {
                unsigned run = above_end;
                #pragma unroll
                for (int i = 7; i >= 0; --i) {
                    run += s_hist[tid * 8 + i];
                    if (run >= Sp) { s_posthr = tid * 8 + i; break; }
                }
            }
        }
    }
    __syncthreads();
    int posthr = s_posthr, negthr = s_negthr;

    if (blockIdx.x == 0 && tid == 0) {
        unsigned tv = 0;
        if (M > 0.0f) tv += totalpos;   // upper bound on valid count
        if (m < 0.0f) tv += totalneg;
        g_totalvalid = tv;
    }

    // ---- compact + warp-cooperative decode ----
    int i = blockIdx.x * 1024 + tid;
    bool inb = (i < NTOT);
    float c = inb ? g_conf[i] : 0.0f;
    int bin = (int)(enc_ord(c) >> 19);
    bool take = inb && (bin >= posthr || bin <= negthr);
    unsigned key = 0u;
    if (take) {
        float score = fmaxf(c * M, c * m);
        if (score > 0.0f) key = ~enc_ord(score);
        else take = false;
    }
    unsigned pos = 0;
    if (take) {
        pos = atomicAdd(&g_ticket, 1u);
        if (pos < CCAP) { g_candK[pos] = key; g_candV[pos] = (unsigned)i; }
        else            { g_overflow = 1u; take = false; }
    }
    unsigned tb = __ballot_sync(0xffffffffu, take);
    while (tb) {
        int src = __ffs(tb) - 1; tb &= tb - 1;
        int cgw = (int)__shfl_sync(0xffffffffu, (unsigned)i, src);
        unsigned cpos = __shfl_sync(0xffffffffu, pos, src);
        int H, abase, local;
        const float* p = box_ptr(cgw, g0, g1, g2, H, abase, local);
        float bvv = -3.4e38f;
        int bi = 0;
        for (int cc = lane; cc < 80; cc += 32) {
            float v = p[5 + cc];
            if (v > bvv) { bvv = v; bi = cc; }
        }
        #pragma unroll
        for (int off = 16; off; off >>= 1) {
            float ov = __shfl_xor_sync(0xffffffffu, bvv, off);
            int   oi = __shfl_xor_sync(0xffffffffu, bi, off);
            if (ov > bvv || (ov == bvv && oi < bi)) { bvv = ov; bi = oi; }
        }
        if (lane == 0) {
            g_candBox[cpos] = geom(p, local, H, abase, anch);
            g_candCls[cpos] = bi;
        }
    }
}

// ---------------- K4: 256-thread tail: bitonic sort + matrix NMS + output + self-clean ----------------
__global__ void __launch_bounds__(K4T, 1)
k4_kernel(const float* __restrict__ g0,
          const float* __restrict__ g1,
          const float* __restrict__ g2,
          const float* __restrict__ anch,
          float* __restrict__ out, int out_size) {
    extern __shared__ unsigned char DS[];
    unsigned long long* A = (unsigned long long*)DS;        // 32KB (4096 u64)
    unsigned* SL = (unsigned*)(DS + 32768);                 // 16KB
    float4*  sBox = (float4*)(DS + 49152);                  // 64KB

    __shared__ unsigned mat[K4T][8];      // suppression bitmatrix (8KB)
    __shared__ float s_areaC[K4T];
    __shared__ unsigned s_alive[8];
    __shared__ int s_opos[MAXB];
    __shared__ int s_fbidx[MAXB];
    __shared__ float4 selB[MAXB];
    __shared__ float  selA[MAXB];
    __shared__ float4 o_box[MAXB];
    __shared__ float  o_score[MAXB];
    __shared__ int    o_cls[MAXB];
    __shared__ float  s_fM[K4T], s_fm[K4T];
    __shared__ int s_nsel;

    const int tid = threadIdx.x;
    const int lane = tid & 31;
    const int wid = tid >> 5;

    unsigned totalvalid = g_totalvalid;
    int C = (int)(g_ticket < (unsigned)CCAP ? g_ticket : (unsigned)CCAP);
    int ovf = (int)g_overflow;
    if (tid == 0) s_nsel = 0;
    __syncthreads();

    if (C > 0) {
        int NP = 128;
        while (NP < C) NP <<= 1;   // <= CCAP = 4096

        for (int i = tid; i < NP; i += K4T) {
            if (i < C) { A[i] = ((unsigned long long)g_candK[i] << 32) | g_candV[i]; SL[i] = (unsigned)i; }
            else       { A[i] = ~0ull; SL[i] = 0u; }
        }
        __syncthreads();

        // ---- bitonic sort ascending on (key, boxidx): exact order + tie-break ----
        for (int k = 2; k <= NP; k <<= 1) {
            for (int j = k >> 1; j > 0; j >>= 1) {
                for (int i = tid; i < NP; i += K4T) {
                    int ixj = i ^ j;
                    if (ixj > i) {
                        bool up = ((i & k) == 0);
                        unsigned long long a = A[i], bb = A[ixj];
                        if ((up && a > bb) || (!up && a < bb)) {
                            A[i] = bb; A[ixj] = a;
                            unsigned t = SL[i]; SL[i] = SL[ixj]; SL[ixj] = t;
                        }
                    }
                }
                __syncthreads();
            }
        }

        // ---- gather candidate boxes in sorted order ----
        for (int i = tid; i < C; i += K4T) sBox[i] = g_candBox[SL[i]];
        __syncthreads();

        // ---- chunked matrix NMS ----
        for (int base = 0; base < C; base += K4T) {
            int t = base + tid;
            int lim = (C - base) < K4T ? (C - base) : K4T;
            bool alive = (tid < lim);
            float4 bx = make_float4(0.f, 0.f, 0.f, 0.f);
            float ar = 0.f;
            if (alive) {
                bx = sBox[t];
                ar = (bx.z - bx.x) * (bx.w - bx.y);
            }
            s_areaC[tid] = ar;
            if (alive) {
                int n0 = s_nsel;
                for (int s = 0; s < n0; ++s) {
                    if (iou_gt_half(bx, ar, selB[s], selA[s])) { alive = false; break; }
                }
            }
            __syncthreads();

            unsigned row[8] = {0u,0u,0u,0u,0u,0u,0u,0u};
            if (alive) {
                for (int j = tid + 1; j < lim; ++j) {
                    float4 ob = sBox[base + j];
                    if (iou_gt_half(bx, ar, ob, s_areaC[j])) row[j >> 5] |= 1u << (j & 31);
                }
            }
            #pragma unroll
            for (int q = 0; q < 8; ++q) mat[tid][q] = row[q];

            unsigned bal = __ballot_sync(0xffffffffu, alive);
            if (lane == 0) s_alive[wid] = bal;
            __syncthreads();

            if (wid == 0) {
                int nsel = s_nsel;
                unsigned aw = (lane < 8) ? s_alive[lane] : 0u;
                while (nsel < MAXB) {
                    unsigned nz = __ballot_sync(0xffffffffu, aw != 0u);
                    if (!nz) break;
                    int fw = __ffs(nz) - 1;
                    unsigned w = __shfl_sync(0xffffffffu, aw, fw);
                    int fb = __ffs(w) - 1;
                    int f = (fw << 5) + fb;
                    if (lane < 8) {
                        aw &= ~mat[f][lane];
                        if (lane == fw) aw &= ~(1u << fb);
                    }
                    if (lane == 0) {
                        int gp = base + f;
                        s_opos[nsel] = gp;
                        float4 sbx = sBox[gp];
                        selB[nsel] = sbx;
                        selA[nsel] = (sbx.z - sbx.x) * (sbx.w - sbx.y);
                    }
                    nsel++;
                }
                if (lane == 0) s_nsel = nsel;
            }
            __syncthreads();
            if (s_nsel >= MAXB) break;
        }

        // ---- fill output arrays ----
        int ns = s_nsel;
        for (int j = tid; j < ns; j += K4T) {
            int i = s_opos[j];
            o_box[j]   = sBox[i];
            o_score[j] = dec_ord(~(unsigned)(A[i] >> 32));
            o_cls[j]   = g_candCls[SL[i]];
        }
        __syncthreads();
    }

    // ================= fallback (exactness guard; normally never taken) =================
    {
        bool need_fb = (s_nsel < MAXB) && (ovf || totalvalid > (unsigned)C);
        if (need_fb) {
            // reduce M/m from partials
            float M = -3.4e38f, m = 3.4e38f;
            for (int i = tid; i < NB1; i += K4T) {
                M = fmaxf(M, g_partM[i]);
                m = fminf(m, g_partm[i]);
            }
            s_fM[tid] = M; s_fm[tid] = m;
            __syncthreads();
            for (int off = K4T / 2; off; off >>= 1) {
                if (tid < off) {
                    s_fM[tid] = fmaxf(s_fM[tid], s_fM[tid + off]);
                    s_fm[tid] = fminf(s_fm[tid], s_fm[tid + off]);
                }
                __syncthreads();
            }
            M = s_fM[0]; m = s_fm[0];
            // compute keys + decode all bboxes
            for (int gw = tid; gw < NTOT; gw += K4T) {
                float c = g_conf[gw];
                float score = fmaxf(c * M, c * m);
                g_keysA[gw] = (score > 0.0f) ? ~enc_ord(score) : 0xFFFFFFFFu;
                int H, abase, local;
                const float* p = box_ptr(gw, g0, g1, g2, H, abase, local);
                g_bboxFB[gw] = geom(p, local, H, abase, anch);
            }
            if (tid == 0) s_nsel = 0;
            __syncthreads();
            unsigned long long* red = A;
            for (int r = 0; r < MAXB; ++r) {
                unsigned long long best = ~0ull;
                for (int i = tid; i < NTOT; i += K4T) {
                    unsigned k = g_keysA[i];
                    if (k < 0x80000000u) {
                        unsigned long long cmp = ((unsigned long long)k << 32) | (unsigned)i;
                        if (cmp < best) best = cmp;
                    }
                }
                red[tid] = best;
                __syncthreads();
                for (int off = K4T / 2; off; off >>= 1) {
                    if (tid < off && red[tid + off] < red[tid]) red[tid] = red[tid + off];
                    __syncthreads();
                }
                best = red[0];
                __syncthreads();
                if (best == ~0ull) break;
                unsigned j = (unsigned)(best & 0xFFFFFFFFu);
                float4 bj = g_bboxFB[j];
                float aj = (bj.z - bj.x) * (bj.w - bj.y);
                if (tid == 0) {
                    int n = s_nsel;
                    o_box[n]   = bj;
                    o_score[n] = dec_ord(~(unsigned)(best >> 32));
                    s_fbidx[n] = (int)j;
                    s_nsel = n + 1;
                }
                for (int i = tid; i < NTOT; i += K4T) {
                    unsigned k = g_keysA[i];
                    if (k < 0x80000000u) {
                        float4 bi = g_bboxFB[i];
                        float ai = (bi.z - bi.x) * (bi.w - bi.y);
                        if (iou_gt_half(bi, ai, bj, aj)) g_keysA[i] = 0xFFFFFFFFu;
                    }
                }
                __syncthreads();
            }
            for (int j2 = tid; j2 < s_nsel; j2 += K4T) {
                int gw = s_fbidx[j2];
                int H, abase, local;
                const float* p = box_ptr(gw, g0, g1, g2, H, abase, local);
                float bestv = -3.4e38f; int bi = 0;
                for (int cc = 0; cc < 80; ++cc) {
                    float v = p[5 + cc];
                    if (v > bestv) { bestv = v; bi = cc; }
                }
                o_cls[j2] = bi;
            }
            __syncthreads();
        }
    }

    // ================= output =================
    int ns = s_nsel;
    for (int i = tid; i < out_size; i += K4T) {
        float v = 0.0f;
        if (i < 400) {
            int j = i >> 2;
            if (j < ns) v = ((float*)o_box)[i];
        } else if (i < 500) {
            int j = i - 400;
            if (j < ns) v = o_score[j];
        } else if (i < 600) {
            int j = i - 500;
            if (j < ns) v = (float)o_cls[j];
        } else if (i == 600) {
            v = (float)ns;
        }
        out[i] = v;
    }

    // ---- self-clean persistent state for next launch ----
    __syncthreads();
    for (int i = tid; i < HBINS; i += K4T) g_hist13[i] = 0u;
    if (tid == 0) {
        g_ticket = 0u;
        g_overflow = 0u;
    }
}

// ---------------- launch ----------------
extern "C" void kernel_launch(void* const* d_in, const int* in_sizes, int n_in,
                              void* d_out, int out_size) {
    const float* g0   = (const float*)d_in[0];
    const float* g1   = (const float*)d_in[1];
    const float* g2   = (const float*)d_in[2];
    const float* anch = (const float*)d_in[3];
    float* out = (float*)d_out;

    cudaFuncSetAttribute(k1_kernel, cudaFuncAttributeMaxDynamicSharedMemorySize, K1SM);
    cudaFuncSetAttribute(k4_kernel, cudaFuncAttributeMaxDynamicSharedMemorySize, K4SM);

    k1_kernel<<<NB1, K1T, K1SM>>>(g0, g1, g2);
    k3_kernel<<<GBLK, 1024>>>(g0, g1, g2, anch);
    k4_kernel<<<1, K4T, K4SM>>>(g0, g1, g2, anch, out, out_size);
}

// round 14
// speedup vs baseline: 1.1121x; 1.0076x over previous
#include <cuda_runtime.h>
#include <cuda_bf16.h>

// ---------------- problem constants ----------------
#define N0 6912      // 48*48*3
#define N1 27648     // 96*96*3
#define N2 110592    // 192*192*3
#define NTOT 145152
#define MAXB 100
#define CCAP 4096
#define S_TAIL 256u
#define HBINS 8192   // 13-bit conf histogram
#define GBLK 142     // 142*1024 >= NTOT
// K1 geometry: 128 boxes per block, smem-staged via cp.async
#define NB1 1134     // NTOT/128
#define BPB 128      // boxes per K1 block
#define K1T 256
#define K1SM (BPB * 85 * 4)   // 43520 bytes
// K4
#define K4T 256
#define K4SM 114688  // A(32KB) + SL(16KB) + sBox(64KB)

// ---------------- scratch (device globals; zero-initialized at load) ----------------
__device__ float    g_conf[NTOT];
__device__ unsigned g_keysA[NTOT];        // fallback-only scratch
__device__ unsigned g_hist13[HBINS];      // zeroed by k4 self-clean
__device__ unsigned g_candK[CCAP], g_candV[CCAP];
__device__ float4   g_candBox[CCAP];
__device__ int      g_candCls[CCAP];
__device__ float4   g_bboxFB[NTOT];       // fallback-only scratch
__device__ float    g_partM[NB1], g_partm[NB1];
__device__ unsigned g_totalvalid;
__device__ unsigned g_ticket, g_overflow;

// ---------------- cp.async helpers ----------------
#define CP_ASYNC16(saddr, gptr) \
    asm volatile("cp.async.cg.shared.global [%0], [%1], 16;" \
                 :: "r"(saddr), "l"(gptr) : "memory")
#define CP_ASYNC_COMMIT()  asm volatile("cp.async.commit_group;" ::: "memory")
#define CP_ASYNC_WAIT0()   asm volatile("cp.async.wait_group 0;" ::: "memory")

// order-preserving float<->uint encodings
__device__ __forceinline__ unsigned enc_ord(float f) {
    unsigned u = __float_as_uint(f);
    return (u & 0x80000000u) ? ~u : (u ^ 0x80000000u);
}
__device__ __forceinline__ float dec_ord(unsigned o) {
    unsigned u = (o & 0x80000000u) ? (o ^ 0x80000000u) : ~o;
    return __uint_as_float(u);
}

// Exact-equivalent IoU>0.5 test: fast multiply compare with a 1e-4 relative
// guard band; inside the band fall back to the reference's rounded division.
__device__ __forceinline__ bool iou_gt_half(float4 a, float areaA, float4 b, float areaB) {
    float iw = fminf(a.z, b.z) - fmaxf(a.x, b.x); iw = fmaxf(iw, 0.0f);
    float ih = fminf(a.w, b.w) - fmaxf(a.y, b.y); ih = fmaxf(ih, 0.0f);
    float inter = iw * ih;
    float U = areaA + areaB - inter;
    float d = inter - 0.5f * U;
    if (fabsf(d) > 1e-4f * U) return d > 0.0f;
    return __fdiv_rn(inter, U) > 0.5f;
}

__device__ __forceinline__ const float* box_ptr(int gw,
        const float* g0, const float* g1, const float* g2,
        int& H, int& abase, int& local) {
    if (gw < N0)      { H = 48;  abase = 12; local = gw;           return g0 + (size_t)local * 85; }
    if (gw < N0 + N1) { H = 96;  abase = 6;  local = gw - N0;      return g1 + (size_t)local * 85; }
    H = 192; abase = 0; local = gw - N0 - N1; return g2 + (size_t)local * 85;
}

__device__ __forceinline__ float4 geom(const float* p, int local, int H, int abase,
                                       const float* anch) {
    float x = p[0], y = p[1], wv = p[2], hv = p[3];
    int a = local % 3;
    int cell = local / 3;
    int cx = cell % H;   // W == H
    int cy = cell / H;
    float aw = anch[abase + a * 2 + 0];
    float ah = anch[abase + a * 2 + 1];
    float bw = expf(wv) * aw;
    float bh = expf(hv) * ah;
    float Hf = (float)H;
    float X = __fdiv_rn(x + (float)cx, Hf);
    float Y = __fdiv_rn(y + (float)cy, Hf);
    return make_float4(X - bw * 0.5f, Y - bh * 0.5f, X + bw * 0.5f, Y + bh * 0.5f);
}

// ---------------- K1: cp.async-staged conf + conf-hist + per-block M/m ----------------
__global__ void __launch_bounds__(K1T)
k1_kernel(const float* __restrict__ g0,
          const float* __restrict__ g1,
          const float* __restrict__ g2) {
    extern __shared__ float S[];
    const int b = blockIdx.x;
    const int tid = threadIdx.x;
    const int lane = tid & 31;
    const int wid = tid >> 5;

    const float* src; int boxbase; int gbase;
    if (b < 54)       { src = g0; boxbase = b * BPB;         gbase = 0; }
    else if (b < 270) { src = g1; boxbase = (b - 54) * BPB;  gbase = N0; }
    else              { src = g2; boxbase = (b - 270) * BPB; gbase = N0 + N1; }

    // async bulk stage-in: 128 boxes * 85 floats = 2720 float4, no register dependency
    const float4* in = (const float4*)(src + (size_t)boxbase * 85);
    unsigned sbase = (unsigned)__cvta_generic_to_shared(S);
    const int NF4 = BPB * 85 / 4;   // 2720
    #pragma unroll 11
    for (int i = tid; i < NF4; i += K1T)
        CP_ASYNC16(sbase + i * 16, in + i);
    CP_ASYNC_COMMIT();
    CP_ASYNC_WAIT0();
    __syncthreads();

    // 2 threads per box: halves of the 80 class probs
    int box = tid >> 1, half = tid & 1;
    const float* pb = S + box * 85;
    float mx = -3.4e38f;
    int base = 5 + half * 40;
    #pragma unroll 8
    for (int i = 0; i < 40; ++i) mx = fmaxf(mx, pb[base + i]);
    mx = fmaxf(mx, __shfl_xor_sync(0xffffffffu, mx, 1));
    if (half == 0) {
        float c = pb[4];
        g_conf[gbase + boxbase + box] = c;
        atomicAdd(&g_hist13[enc_ord(c) >> 19], 1u);
    }

    float M = mx, m = mx;
    #pragma unroll
    for (int off = 16; off > 1; off >>= 1) {
        M = fmaxf(M, __shfl_xor_sync(0xffffffffu, M, off));
        m = fminf(m, __shfl_xor_sync(0xffffffffu, m, off));
    }
    __shared__ float aM[8], am[8];
    if (lane == 0) { aM[wid] = M; am[wid] = m; }
    __syncthreads();
    if (tid == 0) {
        #pragma unroll
        for (int i = 1; i < 8; ++i) { M = fmaxf(M, aM[i]); m = fminf(m, am[i]); }
        g_partM[b] = M;
        g_partm[b] = m;
    }
}

// ---------------- K3: per-block two-tail cutoff + compact + warp-cooperative decode ----------------
__global__ void __launch_bounds__(1024)
k3_kernel(const float* __restrict__ g0,
          const float* __restrict__ g1,
          const float* __restrict__ g2,
          const float* __restrict__ anch) {
    __shared__ unsigned s_hist[HBINS];   // 32KB
    __shared__ unsigned s_part[1024];    // 4KB
    __shared__ float s_rM[32], s_rm[32];
    __shared__ float s_MM, s_mm;
    __shared__ int s_posthr, s_negthr;

    const int tid = threadIdx.x;
    const int lane = tid & 31;
    const int wid = tid >> 5;

    // ---- reduce partial M/m (all blocks redundantly) ----
    {
        float M = -3.4e38f, m = 3.4e38f;
        for (int i = tid; i < NB1; i += 1024) {
            M = fmaxf(M, g_partM[i]);
            m = fminf(m, g_partm[i]);
        }
        #pragma unroll
        for (int off = 16; off; off >>= 1) {
            M = fmaxf(M, __shfl_xor_sync(0xffffffffu, M, off));
            m = fminf(m, __shfl_xor_sync(0xffffffffu, m, off));
        }
        if (lane == 0) { s_rM[wid] = M; s_rm[wid] = m; }
        __syncthreads();
        if (tid == 0) {
            #pragma unroll
            for (int i = 1; i < 32; ++i) { M = fmaxf(M, s_rM[i]); m = fminf(m, s_rm[i]); }
            s_MM = M; s_mm = m;
            s_posthr = 0x7FFFFFFF;
            s_negthr = -1;
        }
    }

    // ---- load conf-hist, prefix sums ----
    #pragma unroll
    for (int i = 0; i < HBINS / 1024; ++i)
        s_hist[tid + i * 1024] = g_hist13[tid + i * 1024];
    __syncthreads();
    unsigned part = 0;
    #pragma unroll
    for (int i = 0; i < 8; ++i) part += s_hist[tid * 8 + i];
    s_part[tid] = part;
    __syncthreads();
    unsigned x = part;
    for (int off = 1; off < 1024; off <<= 1) {
        unsigned add = (tid >= off) ? s_part[tid - off] : 0u;
        __syncthreads();
        x += add;
        s_part[tid] = x;
        __syncthreads();
    }
    const unsigned TOT = s_part[1023];
    const unsigned totalneg = s_part[511];         // bins 0..4095 (c<0 incl -0)
    const unsigned totalpos = TOT - totalneg;      // bins 4096..8191 (c>0 incl +0)
    const float M = s_MM, m = s_mm;

    // ---- neg tail threshold (valid iff m<0): top scores = most negative conf = lowest bins ----
    if (m < 0.0f && totalneg > 0) {
        unsigned Sn = S_TAIL < totalneg ? S_TAIL : totalneg;
        if (tid < 512) {
            unsigned prev = (tid == 0) ? 0u : s_part[tid - 1];
            if (x >= Sn && prev < Sn) {
                unsigned run = prev;
                #pragma unroll
                for (int i = 0; i < 8; ++i) {
                    run += s_hist[tid * 8 + i];
                    if (run >= Sn) { s_negthr = tid * 8 + i; break; }
                }
            }
        }
    }
    // ---- pos tail threshold (valid iff M>0): top scores = highest conf = highest bins ----
    if (M > 0.0f && totalpos > 0) {
        unsigned Sp = S_TAIL < totalpos ? S_TAIL : totalpos;
        if (tid >= 512) {
            unsigned above_end = TOT - x;                       // bins > 8*tid+7
            unsigned above_start = TOT - s_part[tid - 1];      // bins >= 8*tid
            if (above_end < Sp && above_start >= Sp) {
                unsigned run = above_end;
                #pragma unroll
                for (int i = 7; i >= 0; --i) {
                    run += s_hist[tid * 8 + i];
                    if (run >= Sp) { s_posthr = tid * 8 + i; break; }
                }
            }
        }
    }
    __syncthreads();
    int posthr = s_posthr, negthr = s_negthr;

    if (blockIdx.x == 0 && tid == 0) {
        unsigned tv = 0;
        if (M > 0.0f) tv += totalpos;   // upper bound on valid count
        if (m < 0.0f) tv += totalneg;
        g_totalvalid = tv;
    }

    // ---- compact + warp-cooperative decode ----
    int i = blockIdx.x * 1024 + tid;
    bool inb = (i < NTOT);
    float c = inb ? g_conf[i] : 0.0f;
    int bin = (int)(enc_ord(c) >> 19);
    bool take = inb && (bin >= posthr || bin <= negthr);
    unsigned key = 0u;
    if (take) {
        float score = fmaxf(c * M, c * m);
        if (score > 0.0f) key = ~enc_ord(score);
        else take = false;
    }
    unsigned pos = 0;
    if (take) {
        pos = atomicAdd(&g_ticket, 1u);
        if (pos < CCAP) { g_candK[pos] = key; g_candV[pos] = (unsigned)i; }
        else            { g_overflow = 1u; take = false; }
    }
    unsigned tb = __ballot_sync(0xffffffffu, take);
    while (tb) {
        int src = __ffs(tb) - 1; tb &= tb - 1;
        int cgw = (int)__shfl_sync(0xffffffffu, (unsigned)i, src);
        unsigned cpos = __shfl_sync(0xffffffffu, pos, src);
        int H, abase, local;
        const float* p = box_ptr(cgw, g0, g1, g2, H, abase, local);
        float bvv = -3.4e38f;
        int bi = 0;
        for (int cc = lane; cc < 80; cc += 32) {
            float v = p[5 + cc];
            if (v > bvv) { bvv = v; bi = cc; }
        }
        #pragma unroll
        for (int off = 16; off; off >>= 1) {
            float ov = __shfl_xor_sync(0xffffffffu, bvv, off);
            int   oi = __shfl_xor_sync(0xffffffffu, bi, off);
            if (ov > bvv || (ov == bvv && oi < bi)) { bvv = ov; bi = oi; }
        }
        if (lane == 0) {
            g_candBox[cpos] = geom(p, local, H, abase, anch);
            g_candCls[cpos] = bi;
        }
    }
}

// ---------------- K4: 256-thread tail: bitonic sort + matrix NMS + output + self-clean ----------------
__global__ void __launch_bounds__(K4T, 1)
k4_kernel(const float* __restrict__ g0,
          const float* __restrict__ g1,
          const float* __restrict__ g2,
          const float* __restrict__ anch,
          float* __restrict__ out, int out_size) {
    extern __shared__ unsigned char DS[];
    unsigned long long* A = (unsigned long long*)DS;        // 32KB (4096 u64)
    unsigned* SL = (unsigned*)(DS + 32768);                 // 16KB
    float4*  sBox = (float4*)(DS + 49152);                  // 64KB

    __shared__ unsigned mat[K4T][8];      // suppression bitmatrix (8KB)
    __shared__ float s_areaC[K4T];
    __shared__ unsigned s_alive[8];
    __shared__ int s_opos[MAXB];
    __shared__ int s_fbidx[MAXB];
    __shared__ float4 selB[MAXB];
    __shared__ float  selA[MAXB];
    __shared__ float4 o_box[MAXB];
    __shared__ float  o_score[MAXB];
    __shared__ int    o_cls[MAXB];
    __shared__ float  s_fM[K4T], s_fm[K4T];
    __shared__ int s_nsel;

    const int tid = threadIdx.x;
    const int lane = tid & 31;
    const int wid = tid >> 5;

    unsigned totalvalid = g_totalvalid;
    int C = (int)(g_ticket < (unsigned)CCAP ? g_ticket : (unsigned)CCAP);
    int ovf = (int)g_overflow;
    if (tid == 0) s_nsel = 0;
    __syncthreads();

    if (C > 0) {
        int NP = 128;
        while (NP < C) NP <<= 1;   // <= CCAP = 4096

        for (int i = tid; i < NP; i += K4T) {
            if (i < C) { A[i] = ((unsigned long long)g_candK[i] << 32) | g_candV[i]; SL[i] = (unsigned)i; }
            else       { A[i] = ~0ull; SL[i] = 0u; }
        }
        __syncthreads();

        // ---- bitonic sort ascending on (key, boxidx): exact order + tie-break ----
        for (int k = 2; k <= NP; k <<= 1) {
            for (int j = k >> 1; j > 0; j >>= 1) {
                for (int i = tid; i < NP; i += K4T) {
                    int ixj = i ^ j;
                    if (ixj > i) {
                        bool up = ((i & k) == 0);
                        unsigned long long a = A[i], bb = A[ixj];
                        if ((up && a > bb) || (!up && a < bb)) {
                            A[i] = bb; A[ixj] = a;
                            unsigned t = SL[i]; SL[i] = SL[ixj]; SL[ixj] = t;
                        }
                    }
                }
                __syncthreads();
            }
        }

        // ---- gather candidate boxes in sorted order ----
        for (int i = tid; i < C; i += K4T) sBox[i] = g_candBox[SL[i]];
        __syncthreads();

        // ---- chunked matrix NMS ----
        for (int base = 0; base < C; base += K4T) {
            int t = base + tid;
            int lim = (C - base) < K4T ? (C - base) : K4T;
            bool alive = (tid < lim);
            float4 bx = make_float4(0.f, 0.f, 0.f, 0.f);
            float ar = 0.f;
            if (alive) {
                bx = sBox[t];
                ar = (bx.z - bx.x) * (bx.w - bx.y);
            }
            s_areaC[tid] = ar;
            if (alive) {
                int n0 = s_nsel;
                for (int s = 0; s < n0; ++s) {
                    if (iou_gt_half(bx, ar, selB[s], selA[s])) { alive = false; break; }
                }
            }
            __syncthreads();

            unsigned row[8] = {0u,0u,0u,0u,0u,0u,0u,0u};
            if (alive) {
                for (int j = tid + 1; j < lim; ++j) {
                    float4 ob = sBox[base + j];
                    if (iou_gt_half(bx, ar, ob, s_areaC[j])) row[j >> 5] |= 1u << (j & 31);
                }
            }
            #pragma unroll
            for (int q = 0; q < 8; ++q) mat[tid][q] = row[q];

            unsigned bal = __ballot_sync(0xffffffffu, alive);
            if (lane == 0) s_alive[wid] = bal;
            __syncthreads();

            if (wid == 0) {
                int nsel = s_nsel;
                unsigned aw = (lane < 8) ? s_alive[lane] : 0u;
                while (nsel < MAXB) {
                    unsigned nz = __ballot_sync(0xffffffffu, aw != 0u);
                    if (!nz) break;
                    int fw = __ffs(nz) - 1;
                    unsigned w = __shfl_sync(0xffffffffu, aw, fw);
                    int fb = __ffs(w) - 1;
                    int f = (fw << 5) + fb;
                    if (lane < 8) {
                        aw &= ~mat[f][lane];
                        if (lane == fw) aw &= ~(1u << fb);
                    }
                    if (lane == 0) {
                        int gp = base + f;
                        s_opos[nsel] = gp;
                        float4 sbx = sBox[gp];
                        selB[nsel] = sbx;
                        selA[nsel] = (sbx.z - sbx.x) * (sbx.w - sbx.y);
                    }
                    nsel++;
                }
                if (lane == 0) s_nsel = nsel;
            }
            __syncthreads();
            if (s_nsel >= MAXB) break;
        }

        // ---- fill output arrays ----
        int ns = s_nsel;
        for (int j = tid; j < ns; j += K4T) {
            int i = s_opos[j];
            o_box[j]   = sBox[i];
            o_score[j] = dec_ord(~(unsigned)(A[i] >> 32));
            o_cls[j]   = g_candCls[SL[i]];
        }
        __syncthreads();
    }

    // ================= fallback (exactness guard; normally never taken) =================
    {
        bool need_fb = (s_nsel < MAXB) && (ovf || totalvalid > (unsigned)C);
        if (need_fb) {
            // reduce M/m from partials
            float M = -3.4e38f, m = 3.4e38f;
            for (int i = tid; i < NB1; i += K4T) {
                M = fmaxf(M, g_partM[i]);
                m = fminf(m, g_partm[i]);
            }
            s_fM[tid] = M; s_fm[tid] = m;
            __syncthreads();
            for (int off = K4T / 2; off; off >>= 1) {
                if (tid < off) {
                    s_fM[tid] = fmaxf(s_fM[tid], s_fM[tid + off]);
                    s_fm[tid] = fminf(s_fm[tid], s_fm[tid + off]);
                }
                __syncthreads();
            }
            M = s_fM[0]; m = s_fm[0];
            // compute keys + decode all bboxes
            for (int gw = tid; gw < NTOT; gw += K4T) {
                float c = g_conf[gw];
                float score = fmaxf(c * M, c * m);
                g_keysA[gw] = (score > 0.0f) ? ~enc_ord(score) : 0xFFFFFFFFu;
                int H, abase, local;
                const float* p = box_ptr(gw, g0, g1, g2, H, abase, local);
                g_bboxFB[gw] = geom(p, local, H, abase, anch);
            }
            if (tid == 0) s_nsel = 0;
            __syncthreads();
            unsigned long long* red = A;
            for (int r = 0; r < MAXB; ++r) {
                unsigned long long best = ~0ull;
                for (int i = tid; i < NTOT; i += K4T) {
                    unsigned k = g_keysA[i];
                    if (k < 0x80000000u) {
                        unsigned long long cmp = ((unsigned long long)k << 32) | (unsigned)i;
                        if (cmp < best) best = cmp;
                    }
                }
                red[tid] = best;
                __syncthreads();
                for (int off = K4T / 2; off; off >>= 1) {
                    if (tid < off && red[tid + off] < red[tid]) red[tid] = red[tid + off];
                    __syncthreads();
                }
                best = red[0];
                __syncthreads();
                if (best == ~0ull) break;
                unsigned j = (unsigned)(best & 0xFFFFFFFFu);
                float4 bj = g_bboxFB[j];
                float aj = (bj.z - bj.x) * (bj.w - bj.y);
                if (tid == 0) {
                    int n = s_nsel;
                    o_box[n]   = bj;
                    o_score[n] = dec_ord(~(unsigned)(best >> 32));
                    s_fbidx[n] = (int)j;
                    s_nsel = n + 1;
                }
                for (int i = tid; i < NTOT; i += K4T) {
                    unsigned k = g_keysA[i];
                    if (k < 0x80000000u) {
                        float4 bi = g_bboxFB[i];
                        float ai = (bi.z - bi.x) * (bi.w - bi.y);
                        if (iou_gt_half(bi, ai, bj, aj)) g_keysA[i] = 0xFFFFFFFFu;
                    }
                }
                __syncthreads();
            }
            for (int j2 = tid; j2 < s_nsel; j2 += K4T) {
                int gw = s_fbidx[j2];
                int H, abase, local;
                const float* p = box_ptr(gw, g0, g1, g2, H, abase, local);
                float bestv = -3.4e38f; int bi = 0;
                for (int cc = 0; cc < 80; ++cc) {
                    float v = p[5 + cc];
                    if (v > bestv) { bestv = v; bi = cc; }
                }
                o_cls[j2] = bi;
            }
            __syncthreads();
        }
    }

    // ================= output =================
    int ns = s_nsel;
    for (int i = tid; i < out_size; i += K4T) {
        float v = 0.0f;
        if (i < 400) {
            int j = i >> 2;
            if (j < ns) v = ((float*)o_box)[i];
        } else if (i < 500) {
            int j = i - 400;
            if (j < ns) v = o_score[j];
        } else if (i < 600) {
            int j = i - 500;
            if (j < ns) v = (float)o_cls[j];
        } else if (i == 600) {
            v = (float)ns;
        }
        out[i] = v;
    }

    // ---- self-clean persistent state for next launch ----
    __syncthreads();
    for (int i = tid; i < HBINS; i += K4T) g_hist13[i] = 0u;
    if (tid == 0) {
        g_ticket = 0u;
        g_overflow = 0u;
    }
}

// ---------------- launch ----------------
extern "C" void kernel_launch(void* const* d_in, const int* in_sizes, int n_in,
                              void* d_out, int out_size) {
    const float* g0   = (const float*)d_in[0];
    const float* g1   = (const float*)d_in[1];
    const float* g2   = (const float*)d_in[2];
    const float* anch = (const float*)d_in[3];
    float* out = (float*)d_out;

    cudaFuncSetAttribute(k1_kernel, cudaFuncAttributeMaxDynamicSharedMemorySize, K1SM);
    cudaFuncSetAttribute(k4_kernel, cudaFuncAttributeMaxDynamicSharedMemorySize, K4SM);

    k1_kernel<<<NB1, K1T, K1SM>>>(g0, g1, g2);
    k3_kernel<<<GBLK, 1024>>>(g0, g1, g2, anch);
    k4_kernel<<<1, K4T, K4SM>>>(g0, g1, g2, anch, out, out_size);
}

// round 15
// speedup vs baseline: 1.1297x; 1.0159x over previous
#include <cuda_runtime.h>
#include <cuda_bf16.h>

// ---------------- problem constants ----------------
#define N0 6912      // 48*48*3
#define N1 27648     // 96*96*3
#define N2 110592    // 192*192*3
#define NTOT 145152
#define MAXB 100
#define CCAP 4096
#define S_TAIL 256u
#define HBINS 8192   // 13-bit conf histogram
#define GBLK 142     // 142*1024 >= NTOT
// K1 geometry: pipelined tiles of 128 boxes
#define BPB 128      // boxes per tile
#define NTILES 1134  // NTOT/128
#define K1NB 296     // 2 blocks per SM
#define K1T 256
#define TILE_F (BPB * 85)          // 10880 floats per tile
#define K1SM (2 * TILE_F * 4)      // 87040 bytes (double buffer)
// K4
#define K4T 256
#define K4SM 114688  // A(32KB) + SL(16KB) + sBox(64KB)

// ---------------- scratch (device globals; zero-initialized at load) ----------------
__device__ float    g_conf[NTOT];
__device__ unsigned g_keysA[NTOT];        // fallback-only scratch
__device__ unsigned g_hist13[HBINS];      // zeroed by k4 self-clean
__device__ unsigned g_candK[CCAP], g_candV[CCAP];
__device__ float4   g_candBox[CCAP];
__device__ int      g_candCls[CCAP];
__device__ float4   g_bboxFB[NTOT];       // fallback-only scratch
__device__ float    g_partM[K1NB], g_partm[K1NB];
__device__ unsigned g_totalvalid;
__device__ unsigned g_ticket, g_overflow;

// ---------------- cp.async helpers ----------------
#define CP_ASYNC16(saddr, gptr) \
    asm volatile("cp.async.cg.shared.global [%0], [%1], 16;" \
                 :: "r"(saddr), "l"(gptr) : "memory")
#define CP_ASYNC_COMMIT()  asm volatile("cp.async.commit_group;" ::: "memory")
#define CP_ASYNC_WAIT0()   asm volatile("cp.async.wait_group 0;" ::: "memory")
#define CP_ASYNC_WAIT1()   asm volatile("cp.async.wait_group 1;" ::: "memory")

// order-preserving float<->uint encodings
__device__ __forceinline__ unsigned enc_ord(float f) {
    unsigned u = __float_as_uint(f);
    return (u & 0x80000000u) ? ~u : (u ^ 0x80000000u);
}
__device__ __forceinline__ float dec_ord(unsigned o) {
    unsigned u = (o & 0x80000000u) ? (o ^ 0x80000000u) : ~o;
    return __uint_as_float(u);
}

// Exact-equivalent IoU>0.5 test: fast multiply compare with a 1e-4 relative
// guard band; inside the band fall back to the reference's rounded division.
__device__ __forceinline__ bool iou_gt_half(float4 a, float areaA, float4 b, float areaB) {
    float iw = fminf(a.z, b.z) - fmaxf(a.x, b.x); iw = fmaxf(iw, 0.0f);
    float ih = fminf(a.w, b.w) - fmaxf(a.y, b.y); ih = fmaxf(ih, 0.0f);
    float inter = iw * ih;
    float U = areaA + areaB - inter;
    float d = inter - 0.5f * U;
    if (fabsf(d) > 1e-4f * U) return d > 0.0f;
    return __fdiv_rn(inter, U) > 0.5f;
}

__device__ __forceinline__ const float* box_ptr(int gw,
        const float* g0, const float* g1, const float* g2,
        int& H, int& abase, int& local) {
    if (gw < N0)      { H = 48;  abase = 12; local = gw;           return g0 + (size_t)local * 85; }
    if (gw < N0 + N1) { H = 96;  abase = 6;  local = gw - N0;      return g1 + (size_t)local * 85; }
    H = 192; abase = 0; local = gw - N0 - N1; return g2 + (size_t)local * 85;
}

__device__ __forceinline__ float4 geom(const float* p, int local, int H, int abase,
                                       const float* anch) {
    float x = p[0], y = p[1], wv = p[2], hv = p[3];
    int a = local % 3;
    int cell = local / 3;
    int cx = cell % H;   // W == H
    int cy = cell / H;
    float aw = anch[abase + a * 2 + 0];
    float ah = anch[abase + a * 2 + 1];
    float bw = expf(wv) * aw;
    float bh = expf(hv) * ah;
    float Hf = (float)H;
    float X = __fdiv_rn(x + (float)cx, Hf);
    float Y = __fdiv_rn(y + (float)cy, Hf);
    return make_float4(X - bw * 0.5f, Y - bh * 0.5f, X + bw * 0.5f, Y + bh * 0.5f);
}

// tile -> source pointer for its first float4
__device__ __forceinline__ const float4* tile_src(int tile,
        const float* g0, const float* g1, const float* g2) {
    if (tile < 54)  return (const float4*)(g0 + (size_t)tile * BPB * 85);
    if (tile < 270) return (const float4*)(g1 + (size_t)(tile - 54) * BPB * 85);
    return (const float4*)(g2 + (size_t)(tile - 270) * BPB * 85);
}

// ---------------- K1: double-buffered pipelined streaming ----------------
__global__ void __launch_bounds__(K1T)
k1_kernel(const float* __restrict__ g0,
          const float* __restrict__ g1,
          const float* __restrict__ g2) {
    extern __shared__ float S[];
    const int b = blockIdx.x;
    const int tid = threadIdx.x;
    const int lane = tid & 31;
    const int wid = tid >> 5;

    float runM = -3.4e38f, runm = 3.4e38f;

    unsigned sb0 = (unsigned)__cvta_generic_to_shared(S);
    unsigned sb1 = sb0 + TILE_F * 4;
    const int NF4 = TILE_F / 4;   // 2720

    // prologue: issue first tile
    if (b < NTILES) {
        const float4* in = tile_src(b, g0, g1, g2);
        #pragma unroll 11
        for (int i = tid; i < NF4; i += K1T)
            CP_ASYNC16(sb0 + i * 16, in + i);
        CP_ASYNC_COMMIT();
    }

    int parity = 0;
    for (int tile = b; tile < NTILES; tile += K1NB) {
        int next = tile + K1NB;
        bool has_next = next < NTILES;
        unsigned sbuf_next = (parity == 0) ? sb1 : sb0;
        if (has_next) {
            const float4* in = tile_src(next, g0, g1, g2);
            #pragma unroll 11
            for (int i = tid; i < NF4; i += K1T)
                CP_ASYNC16(sbuf_next + i * 16, in + i);
            CP_ASYNC_COMMIT();
            CP_ASYNC_WAIT1();
        } else {
            CP_ASYNC_WAIT0();
        }
        __syncthreads();

        // compute on current buffer: 2 threads per box
        const float* B = (parity == 0) ? S : (S + TILE_F);
        int box = tid >> 1, half = tid & 1;
        const float* pb = B + box * 85;
        float mx = -3.4e38f;
        int base = 5 + half * 40;
        #pragma unroll 8
        for (int i = 0; i < 40; ++i) mx = fmaxf(mx, pb[base + i]);
        mx = fmaxf(mx, __shfl_xor_sync(0xffffffffu, mx, 1));
        if (half == 0) {
            float c = pb[4];
            g_conf[tile * BPB + box] = c;
            atomicAdd(&g_hist13[enc_ord(c) >> 19], 1u);
        }
        runM = fmaxf(runM, mx);
        runm = fminf(runm, mx);

        __syncthreads();   // protect buffer reuse by next iteration's issue
        parity ^= 1;
    }

    // block reduce running M/m
    #pragma unroll
    for (int off = 16; off; off >>= 1) {
        runM = fmaxf(runM, __shfl_xor_sync(0xffffffffu, runM, off));
        runm = fminf(runm, __shfl_xor_sync(0xffffffffu, runm, off));
    }
    __shared__ float aM[8], am[8];
    if (lane == 0) { aM[wid] = runM; am[wid] = runm; }
    __syncthreads();
    if (tid == 0) {
        #pragma unroll
        for (int i = 1; i < 8; ++i) { runM = fmaxf(runM, aM[i]); runm = fminf(runm, am[i]); }
        g_partM[b] = runM;
        g_partm[b] = runm;
    }
}

// ---------------- K3: per-block two-tail cutoff + compact + warp-cooperative decode ----------------
__global__ void __launch_bounds__(1024)
k3_kernel(const float* __restrict__ g0,
          const float* __restrict__ g1,
          const float* __restrict__ g2,
          const float* __restrict__ anch) {
    __shared__ unsigned s_hist[HBINS];   // 32KB
    __shared__ unsigned s_part[1024];    // 4KB
    __shared__ float s_rM[32], s_rm[32];
    __shared__ float s_MM, s_mm;
    __shared__ int s_posthr, s_negthr;

    const int tid = threadIdx.x;
    const int lane = tid & 31;
    const int wid = tid >> 5;

    // ---- reduce partial M/m (all blocks redundantly) ----
    {
        float M = -3.4e38f, m = 3.4e38f;
        if (tid < K1NB) { M = g_partM[tid]; m = g_partm[tid]; }
        #pragma unroll
        for (int off = 16; off; off >>= 1) {
            M = fmaxf(M, __shfl_xor_sync(0xffffffffu, M, off));
            m = fminf(m, __shfl_xor_sync(0xffffffffu, m, off));
        }
        if (lane == 0) { s_rM[wid] = M; s_rm[wid] = m; }
        __syncthreads();
        if (tid == 0) {
            #pragma unroll
            for (int i = 1; i < 32; ++i) { M = fmaxf(M, s_rM[i]); m = fminf(m, s_rm[i]); }
            s_MM = M; s_mm = m;
            s_posthr = 0x7FFFFFFF;
            s_negthr = -1;
        }
    }

    // ---- load conf-hist, prefix sums ----
    #pragma unroll
    for (int i = 0; i < HBINS / 1024; ++i)
        s_hist[tid + i * 1024] = g_hist13[tid + i * 1024];
    __syncthreads();
    unsigned part = 0;
    #pragma unroll
    for (int i = 0; i < 8; ++i) part += s_hist[tid * 8 + i];
    s_part[tid] = part;
    __syncthreads();
    unsigned x = part;
    for (int off = 1; off < 1024; off <<= 1) {
        unsigned add = (tid >= off) ? s_part[tid - off] : 0u;
        __syncthreads();
        x += add;
        s_part[tid] = x;
        __syncthreads();
    }
    const unsigned TOT = s_part[1023];
    const unsigned totalneg = s_part[511];         // bins 0..4095 (c<0 incl -0)
    const unsigned totalpos = TOT - totalneg;      // bins 4096..8191 (c>0 incl +0)
    const float M = s_MM, m = s_mm;

    // ---- neg tail threshold (valid iff m<0): top scores = most negative conf = lowest bins ----
    if (m < 0.0f && totalneg > 0) {
        unsigned Sn = S_TAIL < totalneg ? S_TAIL : totalneg;
        if (tid < 512) {
            unsigned prev = (tid == 0) ? 0u : s_part[tid - 1];
            if (x >= Sn && prev < Sn) {
                unsigned run = prev;
                #pragma unroll
                for (int i = 0; i < 8; ++i) {
                    run += s_hist[tid * 8 + i];
                    if (run >= Sn) { s_negthr = tid * 8 + i; break; }
                }
            }
        }
    }
    // ---- pos tail threshold (valid iff M>0): top scores = highest conf = highest bins ----
    if (M > 0.0f && totalpos > 0) {
        unsigned Sp = S_TAIL < totalpos ? S_TAIL : totalpos;
        if (tid >= 512) {
            unsigned above_end = TOT - x;                       // bins > 8*tid+7
            unsigned above_start = TOT - s_part[tid - 1];      // bins >= 8*tid
            if (above_end < Sp && above_start >= Sp) {
                unsigned run = above_end;
                #pragma unroll
                for (int i = 7; i >= 0; --i) {
                    run += s_hist[tid * 8 + i];
                    if (run >= Sp) { s_posthr = tid * 8 + i; break; }
                }
            }
        }
    }
    __syncthreads();
    int posthr = s_posthr, negthr = s_negthr;

    if (blockIdx.x == 0 && tid == 0) {
        unsigned tv = 0;
        if (M > 0.0f) tv += totalpos;   // upper bound on valid count
        if (m < 0.0f) tv += totalneg;
        g_totalvalid = tv;
    }

    // ---- compact + warp-cooperative decode ----
    int i = blockIdx.x * 1024 + tid;
    bool inb = (i < NTOT);
    float c = inb ? g_conf[i] : 0.0f;
    int bin = (int)(enc_ord(c) >> 19);
    bool take = inb && (bin >= posthr || bin <= negthr);
    unsigned key = 0u;
    if (take) {
        float score = fmaxf(c * M, c * m);
        if (score > 0.0f) key = ~enc_ord(score);
        else take = false;
    }
    unsigned pos = 0;
    if (take) {
        pos = atomicAdd(&g_ticket, 1u);
        if (pos < CCAP) { g_candK[pos] = key; g_candV[pos] = (unsigned)i; }
        else            { g_overflow = 1u; take = false; }
    }
    unsigned tb = __ballot_sync(0xffffffffu, take);
    while (tb) {
        int src = __ffs(tb) - 1; tb &= tb - 1;
        int cgw = (int)__shfl_sync(0xffffffffu, (unsigned)i, src);
        unsigned cpos = __shfl_sync(0xffffffffu, pos, src);
        int H, abase, local;
        const float* p = box_ptr(cgw, g0, g1, g2, H, abase, local);
        float bvv = -3.4e38f;
        int bi = 0;
        for (int cc = lane; cc < 80; cc += 32) {
            float v = p[5 + cc];
            if (v > bvv) { bvv = v; bi = cc; }
        }
        #pragma unroll
        for (int off = 16; off; off >>= 1) {
            float ov = __shfl_xor_sync(0xffffffffu, bvv, off);
            int   oi = __shfl_xor_sync(0xffffffffu, bi, off);
            if (ov > bvv || (ov == bvv && oi < bi)) { bvv = ov; bi = oi; }
        }
        if (lane == 0) {
            g_candBox[cpos] = geom(p, local, H, abase, anch);
            g_candCls[cpos] = bi;
        }
    }
}

// ---------------- K4: 256-thread tail: bitonic sort + matrix NMS + output + self-clean ----------------
__global__ void __launch_bounds__(K4T, 1)
k4_kernel(const float* __restrict__ g0,
          const float* __restrict__ g1,
          const float* __restrict__ g2,
          const float* __restrict__ anch,
          float* __restrict__ out, int out_size) {
    extern __shared__ unsigned char DS[];
    unsigned long long* A = (unsigned long long*)DS;        // 32KB (4096 u64)
    unsigned* SL = (unsigned*)(DS + 32768);                 // 16KB
    float4*  sBox = (float4*)(DS + 49152);                  // 64KB

    __shared__ unsigned mat[K4T][8];      // suppression bitmatrix (8KB)
    __shared__ float s_areaC[K4T];
    __shared__ unsigned s_alive[8];
    __shared__ int s_opos[MAXB];
    __shared__ int s_fbidx[MAXB];
    __shared__ float4 selB[MAXB];
    __shared__ float  selA[MAXB];
    __shared__ float4 o_box[MAXB];
    __shared__ float  o_score[MAXB];
    __shared__ int    o_cls[MAXB];
    __shared__ float  s_fM[K4T], s_fm[K4T];
    __shared__ int s_nsel;

    const int tid = threadIdx.x;
    const int lane = tid & 31;
    const int wid = tid >> 5;

    unsigned totalvalid = g_totalvalid;
    int C = (int)(g_ticket < (unsigned)CCAP ? g_ticket : (unsigned)CCAP);
    int ovf = (int)g_overflow;
    if (tid == 0) s_nsel = 0;
    __syncthreads();

    if (C > 0) {
        int NP = 128;
        while (NP < C) NP <<= 1;   // <= CCAP = 4096

        for (int i = tid; i < NP; i += K4T) {
            if (i < C) { A[i] = ((unsigned long long)g_candK[i] << 32) | g_candV[i]; SL[i] = (unsigned)i; }
            else       { A[i] = ~0ull; SL[i] = 0u; }
        }
        __syncthreads();

        // ---- bitonic sort ascending on (key, boxidx): exact order + tie-break ----
        for (int k = 2; k <= NP; k <<= 1) {
            for (int j = k >> 1; j > 0; j >>= 1) {
                for (int i = tid; i < NP; i += K4T) {
                    int ixj = i ^ j;
                    if (ixj > i) {
                        bool up = ((i & k) == 0);
                        unsigned long long a = A[i], bb = A[ixj];
                        if ((up && a > bb) || (!up && a < bb)) {
                            A[i] = bb; A[ixj] = a;
                            unsigned t = SL[i]; SL[i] = SL[ixj]; SL[ixj] = t;
                        }
                    }
                }
                __syncthreads();
            }
        }

        // ---- gather candidate boxes in sorted order ----
        for (int i = tid; i < C; i += K4T) sBox[i] = g_candBox[SL[i]];
        __syncthreads();

        // ---- chunked matrix NMS ----
        for (int base = 0; base < C; base += K4T) {
            int t = base + tid;
            int lim = (C - base) < K4T ? (C - base) : K4T;
            bool alive = (tid < lim);
            float4 bx = make_float4(0.f, 0.f, 0.f, 0.f);
            float ar = 0.f;
            if (alive) {
                bx = sBox[t];
                ar = (bx.z - bx.x) * (bx.w - bx.y);
            }
            s_areaC[tid] = ar;
            if (alive) {
                int n0 = s_nsel;
                for (int s = 0; s < n0; ++s) {
                    if (iou_gt_half(bx, ar, selB[s], selA[s])) { alive = false; break; }
                }
            }
            __syncthreads();

            unsigned row[8] = {0u,0u,0u,0u,0u,0u,0u,0u};
            if (alive) {
                for (int j = tid + 1; j < lim; ++j) {
                    float4 ob = sBox[base + j];
                    if (iou_gt_half(bx, ar, ob, s_areaC[j])) row[j >> 5] |= 1u << (j & 31);
                }
            }
            #pragma unroll
            for (int q = 0; q < 8; ++q) mat[tid][q] = row[q];

            unsigned bal = __ballot_sync(0xffffffffu, alive);
            if (lane == 0) s_alive[wid] = bal;
            __syncthreads();

            if (wid == 0) {
                int nsel = s_nsel;
                unsigned aw = (lane < 8) ? s_alive[lane] : 0u;
                while (nsel < MAXB) {
                    unsigned nz = __ballot_sync(0xffffffffu, aw != 0u);
                    if (!nz) break;
                    int fw = __ffs(nz) - 1;
                    unsigned w = __shfl_sync(0xffffffffu, aw, fw);
                    int fb = __ffs(w) - 1;
                    int f = (fw << 5) + fb;
                    if (lane < 8) {
                        aw &= ~mat[f][lane];
                        if (lane == fw) aw &= ~(1u << fb);
                    }
                    if (lane == 0) {
                        int gp = base + f;
                        s_opos[nsel] = gp;
                        float4 sbx = sBox[gp];
                        selB[nsel] = sbx;
                        selA[nsel] = (sbx.z - sbx.x) * (sbx.w - sbx.y);
                    }
                    nsel++;
                }
                if (lane == 0) s_nsel = nsel;
            }
            __syncthreads();
            if (s_nsel >= MAXB) break;
        }

        // ---- fill output arrays ----
        int ns = s_nsel;
        for (int j = tid; j < ns; j += K4T) {
            int i = s_opos[j];
            o_box[j]   = sBox[i];
            o_score[j] = dec_ord(~(unsigned)(A[i] >> 32));
            o_cls[j]   = g_candCls[SL[i]];
        }
        __syncthreads();
    }

    // ================= fallback (exactness guard; normally never taken) =================
    {
        bool need_fb = (s_nsel < MAXB) && (ovf || totalvalid > (unsigned)C);
        if (need_fb) {
            // reduce M/m from partials
            float M = -3.4e38f, m = 3.4e38f;
            for (int i = tid; i < K1NB; i += K4T) {
                M = fmaxf(M, g_partM[i]);
                m = fminf(m, g_partm[i]);
            }
            s_fM[tid] = M; s_fm[tid] = m;
            __syncthreads();
            for (int off = K4T / 2; off; off >>= 1) {
                if (tid < off) {
                    s_fM[tid] = fmaxf(s_fM[tid], s_fM[tid + off]);
                    s_fm[tid] = fminf(s_fm[tid], s_fm[tid + off]);
                }
                __syncthreads();
            }
            M = s_fM[0]; m = s_fm[0];
            // compute keys + decode all bboxes
            for (int gw = tid; gw < NTOT; gw += K4T) {
                float c = g_conf[gw];
                float score = fmaxf(c * M, c * m);
                g_keysA[gw] = (score > 0.0f) ? ~enc_ord(score) : 0xFFFFFFFFu;
                int H, abase, local;
                const float* p = box_ptr(gw, g0, g1, g2, H, abase, local);
                g_bboxFB[gw] = geom(p, local, H, abase, anch);
            }
            if (tid == 0) s_nsel = 0;
            __syncthreads();
            unsigned long long* red = A;
            for (int r = 0; r < MAXB; ++r) {
                unsigned long long best = ~0ull;
                for (int i = tid; i < NTOT; i += K4T) {
                    unsigned k = g_keysA[i];
                    if (k < 0x80000000u) {
                        unsigned long long cmp = ((unsigned long long)k << 32) | (unsigned)i;
                        if (cmp < best) best = cmp;
                    }
                }
                red[tid] = best;
                __syncthreads();
                for (int off = K4T / 2; off; off >>= 1) {
                    if (tid < off && red[tid + off] < red[tid]) red[tid] = red[tid + off];
                    __syncthreads();
                }
                best = red[0];
                __syncthreads();
                if (best == ~0ull) break;
                unsigned j = (unsigned)(best & 0xFFFFFFFFu);
                float4 bj = g_bboxFB[j];
                float aj = (bj.z - bj.x) * (bj.w - bj.y);
                if (tid == 0) {
                    int n = s_nsel;
                    o_box[n]   = bj;
                    o_score[n] = dec_ord(~(unsigned)(best >> 32));
                    s_fbidx[n] = (int)j;
                    s_nsel = n + 1;
                }
                for (int i = tid; i < NTOT; i += K4T) {
                    unsigned k = g_keysA[i];
                    if (k < 0x80000000u) {
                        float4 bi = g_bboxFB[i];
                        float ai = (bi.z - bi.x) * (bi.w - bi.y);
                        if (iou_gt_half(bi, ai, bj, aj)) g_keysA[i] = 0xFFFFFFFFu;
                    }
                }
                __syncthreads();
            }
            for (int j2 = tid; j2 < s_nsel; j2 += K4T) {
                int gw = s_fbidx[j2];
                int H, abase, local;
                const float* p = box_ptr(gw, g0, g1, g2, H, abase, local);
                float bestv = -3.4e38f; int bi = 0;
                for (int cc = 0; cc < 80; ++cc) {
                    float v = p[5 + cc];
                    if (v > bestv) { bestv = v; bi = cc; }
                }
                o_cls[j2] = bi;
            }
            __syncthreads();
        }
    }

    // ================= output =================
    int ns = s_nsel;
    for (int i = tid; i < out_size; i += K4T) {
        float v = 0.0f;
        if (i < 400) {
            int j = i >> 2;
            if (j < ns) v = ((float*)o_box)[i];
        } else if (i < 500) {
            int j = i - 400;
            if (j < ns) v = o_score[j];
        } else if (i < 600) {
            int j = i - 500;
            if (j < ns) v = (float)o_cls[j];
        } else if (i == 600) {
            v = (float)ns;
        }
        out[i] = v;
    }

    // ---- self-clean persistent state for next launch ----
    __syncthreads();
    for (int i = tid; i < HBINS; i += K4T) g_hist13[i] = 0u;
    if (tid == 0) {
        g_ticket = 0u;
        g_overflow = 0u;
    }
}

// ---------------- launch ----------------
extern "C" void kernel_launch(void* const* d_in, const int* in_sizes, int n_in,
                              void* d_out, int out_size) {
    const float* g0   = (const float*)d_in[0];
    const float* g1   = (const float*)d_in[1];
    const float* g2   = (const float*)d_in[2];
    const float* anch = (const float*)d_in[3];
    float* out = (float*)d_out;

    cudaFuncSetAttribute(k1_kernel, cudaFuncAttributeMaxDynamicSharedMemorySize, K1SM);
    cudaFuncSetAttribute(k4_kernel, cudaFuncAttributeMaxDynamicSharedMemorySize, K4SM);

    k1_kernel<<<K1NB, K1T, K1SM>>>(g0, g1, g2);
    k3_kernel<<<GBLK, 1024>>>(g0, g1, g2, anch);
    k4_kernel<<<1, K4T, K4SM>>>(g0, g1, g2, anch, out, out_size);
}